// round 17
// baseline (speedup 1.0000x reference)
#include <cuda_runtime.h>
#include <math.h>

// Fixed problem shapes
#define BH 32            // B*H
#define LL 2048
#define DD 64
#define UU 40            // top-k count
#define SK 40            // sample_k
#define NS 64            // key-chunks (warp-sized)
#define CK 32            // keys per chunk

#define NCUM 128         // cumsum blocks inside the fused kernel
#define NMB  2048        // m blocks inside the fused kernel (32 queries each)

// Scratch (device globals; no allocation allowed)
__device__ float g_M[BH * LL];
__device__ int   g_top[BH * UU];
__device__ float g_acc[BH * UU * DD];   // atomic accumulators (328 KB)
__device__ float g_l[BH * UU];          // atomic softmax denominators

// monotone float -> uint order transform (exact, handles +-inf)
__device__ __forceinline__ unsigned int float_order(float f) {
    unsigned int u = __float_as_uint(f);
    return (u & 0x80000000u) ? ~u : (u | 0x80000000u);
}

// ---------------------------------------------------------------------------
// Kernel 1 (fused): blocks [0,NCUM) = cumsum of V into d_out (DRAM-bound);
// blocks [NCUM,NCUM+NMB) = sparsity metric M (L2-bound). One launch overlaps
// the two memory paths.  block = 1024 threads.
// ---------------------------------------------------------------------------
__global__ void __launch_bounds__(1024) pre_kernel(const float* __restrict__ V,
                                                   float* __restrict__ out,
                                                   const float* __restrict__ Q,
                                                   const float* __restrict__ K,
                                                   const int* __restrict__ idxs) {
    __shared__ float cs[64 * 16];

    if (blockIdx.x < NCUM) {
        // ---- cumsum path ----
        const int bid   = blockIdx.x;
        const int bh    = bid >> 2;
        const int dg    = bid & 3;
        const int dl    = threadIdx.x & 15;
        const int d     = dg * 16 + dl;
        const int chunk = threadIdx.x >> 4;     // 0..63
        const int RPC   = 32;
        const size_t base = (size_t)bh * LL * DD;
        const float* vp = V + base + (size_t)chunk * RPC * DD + d;

        float s = 0.f;
#pragma unroll 8
        for (int i = 0; i < RPC; i++) s += vp[(size_t)i * DD];

        cs[chunk * 16 + dl] = s;
        __syncthreads();

        float off = 0.f;
        for (int c = 0; c < chunk; c++) off += cs[c * 16 + dl];

        float* op = out + base + (size_t)chunk * RPC * DD + d;
        float acc = off;
#pragma unroll 8
        for (int i = 0; i < RPC; i++) {
            acc += vp[(size_t)i * DD];
            op[(size_t)i * DD] = acc;
        }
        return;
    }

    // ---- m path: warp per query, 4 samples/iter in 8-lane groups ----
    const int w    = (blockIdx.x - NCUM) * 32 + (threadIdx.x >> 5);
    const int lane = threadIdx.x & 31;
    const int bh   = w >> 11;        // / 2048
    const int q    = w & (LL - 1);
    const size_t base = (size_t)bh * LL * DD;
    const int g     = lane & 7;      // dim-group within sample
    const int s_sub = lane >> 3;     // which of 4 samples this iteration

    const float4 qa  = __ldg((const float4*)(Q + base + (size_t)q * DD) + g);
    const float4 qb4 = __ldg((const float4*)(Q + base + (size_t)q * DD) + 8 + g);

    const int* ip = idxs + q * SK;
    float lm = -INFINITY, ls = 0.f;
#pragma unroll
    for (int bb = 0; bb < SK; bb += 4) {          // 10 iterations
        const int sidx = __ldg(ip + bb + s_sub);
        const float4 ka = __ldg((const float4*)(K + base + (size_t)sidx * DD) + g);
        const float4 kb = __ldg((const float4*)(K + base + (size_t)sidx * DD) + 8 + g);
        float d = qa.x * ka.x + qa.y * ka.y + qa.z * ka.z + qa.w * ka.w
                + qb4.x * kb.x + qb4.y * kb.y + qb4.z * kb.z + qb4.w * kb.w;
        d += __shfl_xor_sync(0xffffffffu, d, 1);
        d += __shfl_xor_sync(0xffffffffu, d, 2);
        d += __shfl_xor_sync(0xffffffffu, d, 4);
        lm = fmaxf(lm, d);
        ls += d;
    }
    lm = fmaxf(lm, __shfl_xor_sync(0xffffffffu, lm, 8));
    ls += __shfl_xor_sync(0xffffffffu, ls, 8);
    lm = fmaxf(lm, __shfl_xor_sync(0xffffffffu, lm, 16));
    ls += __shfl_xor_sync(0xffffffffu, ls, 16);
    if (lane == 0) g_M[bh * LL + q] = lm - ls * (1.0f / (float)LL);
}

// ---------------------------------------------------------------------------
// Kernel 2: fused top-40 + accumulator zeroing. grid = BH, block = 256.
// ---------------------------------------------------------------------------
__global__ void __launch_bounds__(256) topk_kernel() {
    const int bh   = blockIdx.x;
    const int t    = threadIdx.x;
    const int warp = t >> 5;
    const int lane = t & 31;

    __shared__ unsigned long long keys[8 * UU];

    // zero accumulators for this bh (2560 + 40 floats)
    for (int i = t; i < UU * DD; i += 256) g_acc[bh * UU * DD + i] = 0.f;
    if (t < UU) g_l[bh * UU + t] = 0.f;

    const int ebase = warp * 256 + lane * 8;
    float v[8];
#pragma unroll
    for (int j = 0; j < 8; j++) v[j] = g_M[bh * LL + ebase + j];

    for (int it = 0; it < UU; it++) {
        float bv = -INFINITY; int bj = 0;
#pragma unroll
        for (int j = 0; j < 8; j++)
            if (v[j] > bv) { bv = v[j]; bj = j; }   // ties: lowest j kept
        const unsigned int o    = float_order(bv);
        const unsigned int mo   = __reduce_max_sync(0xffffffffu, o);
        const unsigned int ball = __ballot_sync(0xffffffffu, o == mo);
        const int src  = __ffs(ball) - 1;           // lowest lane = lowest idx
        const int widx = __shfl_sync(0xffffffffu, ebase + bj, src);  // collective
        if (lane == src) v[bj] = -INFINITY;         // winner clears its element
        if (lane == 0)
            keys[warp * UU + it] =
                ((unsigned long long)mo << 32) | (unsigned int)(~widx);
    }
    __syncthreads();

    for (int cand = t; cand < 8 * UU; cand += 256) {
        const unsigned long long my = keys[cand];
        int rank = 0;
#pragma unroll 8
        for (int j = 0; j < 8 * UU; j++)
            rank += (keys[j] > my);
        if (rank < UU)
            g_top[bh * UU + rank] = (int)(~(unsigned int)(my & 0xffffffffu));
    }
}

// ---------------------------------------------------------------------------
// Kernel 3: attention partials via direct atomic accumulation.
// grid = BH*64*2, block = 32. Warp = (chunk c, query-parity half): it handles
// queries u = half, half+2, ... for chunk c. Atomic accumulation makes the
// split free (no merge); halves each warp's serial chain, doubles warp count.
// No max subtraction: scores ~N(0,1), exp(s) <= ~e^6 — fp32-safe.
// ---------------------------------------------------------------------------
__global__ void __launch_bounds__(32) attn_atomic_kernel(const float* __restrict__ Q,
                                                         const float* __restrict__ K,
                                                         const float* __restrict__ V) {
    const int bid  = blockIdx.x;
    const int bh   = bid >> 7;            // / 128
    const int rem  = bid & 127;
    const int c    = rem >> 1;            // chunk 0..63
    const int half = rem & 1;             // query parity
    const int lane = threadIdx.x;
    const size_t base = (size_t)bh * LL * DD;
    const int k0 = c * CK;

    __shared__ int   topS[UU];
    __shared__ float Qs[UU][DD];          // only parity rows filled

    for (int i = lane; i < UU; i += 32) topS[i] = g_top[bh * UU + i];
    __syncwarp();
    // load the 20 Q rows of this warp's parity (20 rows x 16 float4)
    for (int i = lane; i < (UU / 2) * 16; i += 32) {
        const int u = half + ((i >> 4) << 1);
        const int j = i & 15;
        *(float4*)&Qs[u][j * 4] = __ldg((const float4*)(Q + base + (size_t)topS[u] * DD) + j);
    }

    // K row of key (k0+lane) -> 64 regs
    float4 kreg[16];
    const float4* kp = (const float4*)(K + base + (size_t)(k0 + lane) * DD);
#pragma unroll
    for (int j = 0; j < 16; j++) kreg[j] = __ldg(kp + j);

    // V columns: lane owns dims (lane) and (lane+32) over 32 keys -> 64 regs
    float v0[CK], v1[CK];
#pragma unroll
    for (int k = 0; k < CK; k++) {
        v0[k] = __ldg(V + base + (size_t)(k0 + k) * DD + lane);
        v1[k] = __ldg(V + base + (size_t)(k0 + k) * DD + 32 + lane);
    }
    __syncwarp();   // Qs ready

    for (int u = half; u < UU; u += 2) {
        const int pos = topS[u];
        if (k0 > pos) continue;            // masked chunk: contributes nothing
        const int bhu = bh * UU + u;

        float a0 = 0.f, a1 = 0.f, a2 = 0.f, a3 = 0.f;
#pragma unroll
        for (int j = 0; j < 16; j++) {
            const float4 kv = kreg[j];
            const float4 qv = *(const float4*)&Qs[u][j * 4];
            a0 += kv.x * qv.x; a1 += kv.y * qv.y;
            a2 += kv.z * qv.z; a3 += kv.w * qv.w;
        }
        const float s = ((a0 + a1) + (a2 + a3)) * 0.125f;
        const int kg = k0 + lane;
        const float p = (kg <= pos) ? __expf(s) : 0.f;   // no max needed

        float acc0 = 0.f, acc1 = 0.f, accl = 0.f;
#pragma unroll
        for (int k = 0; k < CK; k++) {
            const float pk = __shfl_sync(0xffffffffu, p, k);
            acc0 += pk * v0[k];
            acc1 += pk * v1[k];
            accl += pk;
        }
        atomicAdd(&g_acc[bhu * DD + lane],      acc0);
        atomicAdd(&g_acc[bhu * DD + 32 + lane], acc1);
        if (lane == 0) atomicAdd(&g_l[bhu], accl);
    }
}

// ---------------------------------------------------------------------------
// Kernel 4: finalize — out[bh,pos,d] = g_acc[bhu,d] / g_l[bhu].
// grid = BH*UU/4, block = 256 (4 queries x 64 dims per block).
// ---------------------------------------------------------------------------
__global__ void __launch_bounds__(256) finalize_kernel(float* __restrict__ out) {
    const int bhu = blockIdx.x * 4 + (threadIdx.x >> 6);
    const int d   = threadIdx.x & 63;
    const int bh  = bhu / UU;
    const int pos = g_top[bhu];
    const float L = g_l[bhu];
    out[(size_t)bh * LL * DD + (size_t)pos * DD + d] = g_acc[bhu * DD + d] / L;
}

// ---------------------------------------------------------------------------
extern "C" void kernel_launch(void* const* d_in, const int* in_sizes, int n_in,
                              void* d_out, int out_size) {
    const float* Q   = (const float*)d_in[0];
    const float* K   = (const float*)d_in[1];
    const float* V   = (const float*)d_in[2];
    const int*   idx = (const int*)d_in[3];
    float* out = (float*)d_out;

    pre_kernel<<<NCUM + NMB, 1024>>>(V, out, Q, K, idx);
    topk_kernel<<<BH, 256>>>();
    attn_atomic_kernel<<<BH * 64 * 2, 32>>>(Q, K, V);
    finalize_kernel<<<BH * UU / 4, 256>>>(out);
}